// round 15
// baseline (speedup 1.0000x reference)
#include <cuda_runtime.h>
#include <cstdint>

// Problem constants
#define BB      128
#define TOPK    32
#define MN      64
#define NODES   258        // MAX_NODES + 2
#define HDIM    128
#define G3      384        // 3*H

// ---------------------------------------------------------------------------
// Device scratch
// ---------------------------------------------------------------------------
__device__ uint32_t g_gi_rel32[400 * 256];        // bf16x2 [rel][pair(64)][4]: r,z,n,pad
__device__ float    g_gi_ent[BB * TOPK * G3];
__device__ uint32_t g_gh32 [BB * NODES * 256];    // bf16x2 [node][pair(64)][4]: r,z,n,h

// ---------------------------------------------------------------------------
// Helpers
// ---------------------------------------------------------------------------
__device__ __forceinline__ uint32_t f2bf2(float lo, float hi) {
    uint32_t r;
    asm("cvt.rn.bf16x2.f32 %0, %1, %2;" : "=r"(r) : "f"(hi), "f"(lo));
    return r;
}
__device__ __forceinline__ uint32_t badd2(uint32_t a, uint32_t b) {
    uint32_t r; asm("add.rn.bf16x2 %0, %1, %2;" : "=r"(r) : "r"(a), "r"(b)); return r;
}
__device__ __forceinline__ uint32_t bsub2(uint32_t a, uint32_t b) {
    uint32_t r; asm("sub.rn.bf16x2 %0, %1, %2;" : "=r"(r) : "r"(a), "r"(b)); return r;
}
__device__ __forceinline__ uint32_t bmul2(uint32_t a, uint32_t b) {
    uint32_t r; asm("mul.rn.bf16x2 %0, %1, %2;" : "=r"(r) : "r"(a), "r"(b)); return r;
}
__device__ __forceinline__ uint32_t bfma2(uint32_t a, uint32_t b, uint32_t c) {
    uint32_t r; asm("fma.rn.bf16x2 %0, %1, %2, %3;" : "=r"(r) : "r"(a), "r"(b), "r"(c)); return r;
}
__device__ __forceinline__ uint32_t btanh2(uint32_t x) {
    uint32_t r; asm("tanh.approx.bf16x2 %0, %1;" : "=r"(r) : "r"(x)); return r;
}
#define BHALF2 0x3F003F00u
__device__ __forceinline__ float blo(uint32_t x) { return __uint_as_float(x << 16); }
__device__ __forceinline__ float bhi(uint32_t x) { return __uint_as_float(x & 0xFFFF0000u); }

__device__ __forceinline__ void mma_bf16(float* d, const uint32_t* a, const uint32_t* b) {
    asm volatile(
        "mma.sync.aligned.m16n8k16.row.col.f32.bf16.bf16.f32 "
        "{%0,%1,%2,%3}, {%4,%5,%6,%7}, {%8,%9}, {%0,%1,%2,%3};"
        : "+f"(d[0]), "+f"(d[1]), "+f"(d[2]), "+f"(d[3])
        : "r"(a[0]), "r"(a[1]), "r"(a[2]), "r"(a[3]), "r"(b[0]), "r"(b[1]));
}

// ---------------------------------------------------------------------------
// Kernel 1: fused bf16 mma.sync GEMM, 294 CTAs (one wave @ 2 CTA/SM).
//   gh branch: writes gate-interleaved [node][pair][4] (r,z,n) and, during
//   A-fill, packs h (bf16x2) into slot 3.
// ---------------------------------------------------------------------------
#define APITCH 68
#define OFFA    0
#define OFFB    (128 * APITCH * 4)
#define OFFBIAS (OFFB + 128 * APITCH * 4)
#define OFFRIDX (OFFBIAS + 384 * 4)
#define GEMM_SMEM (OFFRIDX + 128 * 4)

__global__ __launch_bounds__(256, 2) void gemm_mma_kernel(
    const float* __restrict__ node_emb,
    const float* __restrict__ ent_tab,
    const float* __restrict__ rel_tab,
    const float* __restrict__ W_ih,
    const float* __restrict__ W_hh,
    const float* __restrict__ b_ih,
    const float* __restrict__ b_hh,
    const int*   __restrict__ aim_ent,
    uint32_t* __restrict__ out_gh,      // [node][pair][4]
    float* __restrict__ out_gi_ent,
    uint32_t* __restrict__ out_gi_rel)  // [rel][pair][4]
{
    extern __shared__ char sm[];
    uint32_t* As = reinterpret_cast<uint32_t*>(sm + OFFA);
    uint32_t* Bs = reinterpret_cast<uint32_t*>(sm + OFFB);
    float*    sh_bias = reinterpret_cast<float*>(sm + OFFBIAS);
    int*      sh_ridx = reinterpret_cast<int*>(sm + OFFRIDX);

    const int tid  = threadIdx.x;
    const int wid  = tid >> 5;
    const int lane = tid & 31;

    int bx = blockIdx.x;
    const float* A; const int* gather = nullptr; int nrows;
    const float* W; int ldw, woff; const float* bias; float* outf = nullptr;
    int tile, obf = 0, orel = 0;
    if (bx < 258) {
        tile = bx;
        A = node_emb; nrows = BB * NODES;
        W = W_hh; ldw = 128; woff = 0; bias = b_hh; obf = 1;
    } else if (bx < 290) {
        tile = bx - 258;
        A = ent_tab; gather = aim_ent; nrows = BB * TOPK;
        W = W_ih; ldw = 256; woff = 0; bias = b_ih; outf = out_gi_ent;
    } else {
        tile = bx - 290;
        A = rel_tab; nrows = 400;
        W = W_ih; ldw = 256; woff = 128; bias = nullptr; orel = 1;
    }
    const int row0 = tile * 128;

    if (tid < 128) {
        int r = row0 + tid;
        sh_ridx[tid] = (r < nrows) ? (gather ? gather[r] : r) : -1;
    }
    for (int i = tid; i < G3; i += 256)
        sh_bias[i] = bias ? bias[i] : 0.0f;
    __syncthreads();

    // ---- fill A tile once (bf16 pairs); gh branch also packs h into slot 3 ----
    for (int idx = tid; idx < 128 * 32; idx += 256) {
        int i  = idx >> 5;
        int k4 = (idx & 31) << 2;
        int ridx = sh_ridx[i];
        float4 v = make_float4(0.f, 0.f, 0.f, 0.f);
        if (ridx >= 0)
            v = *reinterpret_cast<const float4*>(&A[(size_t)ridx * 128 + k4]);
        uint2 w = make_uint2(f2bf2(v.x, v.y), f2bf2(v.z, v.w));
        *reinterpret_cast<uint2*>(&As[i * APITCH + (k4 >> 1)]) = w;
        if (obf && ridx >= 0) {
            int p0 = k4 >> 1;
            out_gh[(size_t)ridx * 256 + p0 * 4 + 3]       = w.x;
            out_gh[(size_t)ridx * 256 + (p0 + 1) * 4 + 3] = w.y;
        }
    }

    const int quad  = lane >> 2;
    const int tq    = lane & 3;
    const int rbase = (wid >> 2) * 64;
    const int cbase = (wid & 3) * 32;

    for (int gate = 0; gate < 3; gate++) {
        for (int idx = tid; idx < 128 * 32; idx += 256) {
            int n  = idx >> 5;
            int k4 = (idx & 31) << 2;
            float4 v = *reinterpret_cast<const float4*>(
                &W[(size_t)(gate * 128 + n) * ldw + woff + k4]);
            uint2 w = make_uint2(f2bf2(v.x, v.y), f2bf2(v.z, v.w));
            *reinterpret_cast<uint2*>(&Bs[n * APITCH + (k4 >> 1)]) = w;
        }
        __syncthreads();

        float acc[4][4][4];
#pragma unroll
        for (int mt = 0; mt < 4; mt++)
#pragma unroll
            for (int nt = 0; nt < 4; nt++)
#pragma unroll
                for (int r = 0; r < 4; r++) acc[mt][nt][r] = 0.f;

#pragma unroll
        for (int ks = 0; ks < 8; ks++) {
            const int k0 = ks * 8;
            uint32_t af[4][4];
#pragma unroll
            for (int mt = 0; mt < 4; mt++) {
                int r = rbase + mt * 16 + quad;
                af[mt][0] = As[r * APITCH + k0 + tq];
                af[mt][1] = As[(r + 8) * APITCH + k0 + tq];
                af[mt][2] = As[r * APITCH + k0 + tq + 4];
                af[mt][3] = As[(r + 8) * APITCH + k0 + tq + 4];
            }
            uint32_t bf[4][2];
#pragma unroll
            for (int nt = 0; nt < 4; nt++) {
                int c = cbase + nt * 8 + quad;
                bf[nt][0] = Bs[c * APITCH + k0 + tq];
                bf[nt][1] = Bs[c * APITCH + k0 + tq + 4];
            }
#pragma unroll
            for (int mt = 0; mt < 4; mt++)
#pragma unroll
                for (int nt = 0; nt < 4; nt++)
                    mma_bf16(acc[mt][nt], af[mt], bf[nt]);
        }

#pragma unroll
        for (int mt = 0; mt < 4; mt++) {
#pragma unroll
            for (int nt = 0; nt < 4; nt++) {
                const int col = cbase + nt * 8 + tq * 2;
                const float b0 = sh_bias[gate * 128 + col];
                const float b1 = sh_bias[gate * 128 + col + 1];
                const int r1 = row0 + rbase + mt * 16 + quad;
                const int r2 = r1 + 8;
                if (obf) {
                    if (r1 < nrows)
                        out_gh[(size_t)r1 * 256 + (col >> 1) * 4 + gate] =
                            f2bf2(acc[mt][nt][0] + b0, acc[mt][nt][1] + b1);
                    if (r2 < nrows)
                        out_gh[(size_t)r2 * 256 + (col >> 1) * 4 + gate] =
                            f2bf2(acc[mt][nt][2] + b0, acc[mt][nt][3] + b1);
                } else if (orel) {
                    if (r1 < nrows)
                        out_gi_rel[(size_t)r1 * 256 + (col >> 1) * 4 + gate] =
                            f2bf2(acc[mt][nt][0] + b0, acc[mt][nt][1] + b1);
                    if (r2 < nrows)
                        out_gi_rel[(size_t)r2 * 256 + (col >> 1) * 4 + gate] =
                            f2bf2(acc[mt][nt][2] + b0, acc[mt][nt][3] + b1);
                } else {
                    if (r1 < nrows)
                        *reinterpret_cast<float2*>(&outf[(size_t)r1 * G3 + gate * 128 + col]) =
                            make_float2(acc[mt][nt][0] + b0, acc[mt][nt][1] + b1);
                    if (r2 < nrows)
                        *reinterpret_cast<float2*>(&outf[(size_t)r2 * G3 + gate * 128 + col]) =
                            make_float2(acc[mt][nt][2] + b0, acc[mt][nt][3] + b1);
                }
            }
        }
        __syncthreads();
    }
}

// ---------------------------------------------------------------------------
// Kernel 2: GRU aggregation, packed bf16x2; per item ONE LDG.128 for
// (gh_r, gh_z, gh_n, h) + ONE LDG.128 for gi_rel gates. No h/gh staging.
// CTA = (batch, 64-ch chunk); 1024 threads; lane owns a channel pair.
// ---------------------------------------------------------------------------
#define OFF_GIR  0                               // u32 [32*32] = 4096
#define OFF_GIZ  4096
#define OFF_GIN  8192
#define OFF_WORK 12288                           // i32 [2048] = 8192
#define OFF_ACC  20480                           // f32 [32*64] = 8192
#define OFF_PREF 28672                           // i32 [33] pad 144
#define OFF_NUM  28816
#define OFF_AIM  28944
#define AGG_SMEM 29072

__global__ __launch_bounds__(1024, 1) void aggregate_kernel(
    const float*    __restrict__ node_emb,
    const uint32_t* __restrict__ gi_rel32,
    const float*    __restrict__ gi_ent,
    const uint32_t* __restrict__ gh32,          // [node][pair][4]: r,z,n,h
    const int2*     __restrict__ neighbors,
    const int*      __restrict__ nb_num,
    const int*      __restrict__ aim_nodes,
    float* __restrict__ out)
{
    extern __shared__ char smraw[];
    uint32_t* sh_gir  = reinterpret_cast<uint32_t*>(smraw + OFF_GIR);
    uint32_t* sh_giz  = reinterpret_cast<uint32_t*>(smraw + OFF_GIZ);
    uint32_t* sh_gin  = reinterpret_cast<uint32_t*>(smraw + OFF_GIN);
    int*      sh_work = reinterpret_cast<int*>(smraw + OFF_WORK);
    float*    sh_acc  = reinterpret_cast<float*>(smraw + OFF_ACC);
    int*      sh_pref = reinterpret_cast<int*>(smraw + OFF_PREF);
    int*      sh_num  = reinterpret_cast<int*>(smraw + OFF_NUM);
    int*      sh_aim  = reinterpret_cast<int*>(smraw + OFF_AIM);

    const int tid = threadIdx.x;
    const int c   = blockIdx.x;        // 64-channel chunk (0..1)
    const int b   = blockIdx.y;
    const int cc0 = c * 64;

    // ---- base copy node_emb -> out (no smem staging) ----
    for (int idx = tid; idx < 258 * 16; idx += 1024) {
        int n = idx >> 4, q = idx & 15;
        float4 v = *reinterpret_cast<const float4*>(
            &node_emb[((size_t)b * NODES + n) * HDIM + cc0 + q * 4]);
        *reinterpret_cast<float4*>(&out[((size_t)b * NODES + n) * HDIM + cc0 + q * 4]) = v;
    }
    // ---- gi_ent packed bf16x2 per pair ----
    for (int idx = tid; idx < 32 * 96; idx += 1024) {
        int t = idx / 96, q = idx % 96;
        int gate = q >> 5, p = q & 31;
        float2 v = *reinterpret_cast<const float2*>(
            &gi_ent[((size_t)b * TOPK + t) * G3 + gate * 128 + cc0 + 2 * p]);
        uint32_t* dst = (gate == 0 ? sh_gir : gate == 1 ? sh_giz : sh_gin);
        dst[t * 32 + p] = f2bf2(v.x, v.y);
    }
    for (int idx = tid; idx < 2048; idx += 1024)
        sh_acc[idx] = 0.0f;
    if (tid < 32)
        sh_num[tid] = nb_num[b * TOPK + tid];
    if (tid >= 32 && tid < 64) {
        int t = tid - 32;
        int node = aim_nodes[b * TOPK + t];
        unsigned grp = __match_any_sync(0xFFFFFFFFu, node);
        int winner = (31 - __clz(grp)) == t;
        sh_aim[t] = winner ? node : -1;
    }
    __syncthreads();

    // ---- prefix scan over num (warp 0) ----
    if (tid < 32) {
        int s = sh_num[tid];
#pragma unroll
        for (int o = 1; o < 32; o <<= 1) {
            int x = __shfl_up_sync(0xFFFFFFFFu, s, o);
            if (tid >= o) s += x;
        }
        sh_pref[tid + 1] = s;
        if (tid == 0) sh_pref[0] = 0;
    }
    __syncthreads();

    const int V = sh_pref[32];

    // ---- worklist build ----
    for (int idx = tid; idx < TOPK * MN; idx += 1024) {
        int t = idx >> 6, m = idx & 63;
        if (m < sh_num[t]) {
            int2 nb = neighbors[(size_t)b * TOPK * MN + idx];
            sh_work[sh_pref[t] + m] = t | (nb.x << 5) | (nb.y << 15);
        }
    }
    __syncthreads();

    // ---- balanced compute: 32 warps; 2 x LDG.128 per item ----
    const int warp = tid >> 5;
    const int lane = tid & 31;
    const int vbeg = (V * warp) >> 5;
    const int vend = (V * (warp + 1)) >> 5;

    const uint32_t* base_g  = gi_rel32 + (c * 32 + lane) * 4;
    const uint32_t* base_gh = gh32 + (size_t)b * NODES * 256 + (c * 32 + lane) * 4;

    int   cur_t = -1;
    uint32_t gir = 0, giz = 0, gin = 0;
    float acc0 = 0.f, acc1 = 0.f;

    for (int v0 = vbeg; v0 < vend; v0 += 4) {
        const int cnt = min(4, vend - v0);
        int w[4]; uint4 gv[4], hv[4];
#pragma unroll
        for (int j = 0; j < 4; j++) {
            if (j < cnt) {
                w[j] = sh_work[v0 + j];
                int rel = w[j] >> 15;
                int nd  = (w[j] >> 5) & 1023;
                gv[j] = __ldg(reinterpret_cast<const uint4*>(base_g + rel * 256));
                hv[j] = __ldg(reinterpret_cast<const uint4*>(base_gh + nd * 256));
            }
        }
#pragma unroll
        for (int j = 0; j < 4; j++) {
            if (j < cnt) {
                int t = w[j] & 31;
                if (t != cur_t) {               // warp-uniform
                    if (cur_t >= 0) {
                        atomicAdd(&sh_acc[cur_t * 64 + 2 * lane],     acc0);
                        atomicAdd(&sh_acc[cur_t * 64 + 2 * lane + 1], acc1);
                    }
                    acc0 = acc1 = 0.f;
                    cur_t = t;
                    gir = sh_gir[t * 32 + lane];
                    giz = sh_giz[t * 32 + lane];
                    gin = sh_gin[t * 32 + lane];
                }
                uint32_t pre_r = badd2(badd2(gir, gv[j].x), hv[j].x);
                uint32_t r = bfma2(btanh2(bmul2(pre_r, BHALF2)), BHALF2, BHALF2);
                uint32_t pre_z = badd2(badd2(giz, gv[j].y), hv[j].y);
                uint32_t z = bfma2(btanh2(bmul2(pre_z, BHALF2)), BHALF2, BHALF2);
                uint32_t pre_n = bfma2(r, hv[j].z, badd2(gin, gv[j].z));
                uint32_t n = btanh2(pre_n);
                uint32_t hn = bfma2(z, bsub2(hv[j].w, n), n);
                acc0 += blo(hn);
                acc1 += bhi(hn);
            }
        }
    }
    if (cur_t >= 0) {
        atomicAdd(&sh_acc[cur_t * 64 + 2 * lane],     acc0);
        atomicAdd(&sh_acc[cur_t * 64 + 2 * lane + 1], acc1);
    }
    __syncthreads();

    // ---- epilogue: mean + scatter winners (warp t) ----
    {
        const int t = warp;
        const int aim = sh_aim[t];
        if (aim >= 0) {
            const int num = sh_num[t];
            float inv = (num > 0) ? 1.0f / (float)num : 0.f;
            float2 u = make_float2(sh_acc[t * 64 + 2 * lane] * inv,
                                   sh_acc[t * 64 + 2 * lane + 1] * inv);
            *reinterpret_cast<float2*>(
                &out[((size_t)b * NODES + aim) * HDIM + cc0 + 2 * lane]) = u;
        }
    }
}

// ---------------------------------------------------------------------------
// Host launcher
// ---------------------------------------------------------------------------
extern "C" void kernel_launch(void* const* d_in, const int* in_sizes, int n_in,
                              void* d_out, int out_size)
{
    const float* node_emb = (const float*)d_in[0];
    const float* ent_tab  = (const float*)d_in[1];
    const float* rel_tab  = (const float*)d_in[2];
    const float* W_ih     = (const float*)d_in[3];
    const float* W_hh     = (const float*)d_in[4];
    const float* b_ih     = (const float*)d_in[5];
    const float* b_hh     = (const float*)d_in[6];
    const int*   aim_nd   = (const int*)d_in[7];
    const int*   aim_ent  = (const int*)d_in[8];
    const int*   nbrs     = (const int*)d_in[9];
    const int*   nb_num   = (const int*)d_in[10];
    float* out = (float*)d_out;

    float* p_gi_ent; uint32_t *p_gi_rel, *p_gh;
    cudaGetSymbolAddress((void**)&p_gi_rel, g_gi_rel32);
    cudaGetSymbolAddress((void**)&p_gi_ent, g_gi_ent);
    cudaGetSymbolAddress((void**)&p_gh,     g_gh32);

    cudaFuncSetAttribute(gemm_mma_kernel,
        cudaFuncAttributeMaxDynamicSharedMemorySize, GEMM_SMEM);
    cudaFuncSetAttribute(aggregate_kernel,
        cudaFuncAttributeMaxDynamicSharedMemorySize, AGG_SMEM);

    // 1) fused GEMMs (bf16 tensor cores, one wave) + h packing
    gemm_mma_kernel<<<294, 256, GEMM_SMEM>>>(
        node_emb, ent_tab, rel_tab, W_ih, W_hh, b_ih, b_hh, aim_ent,
        p_gh, p_gi_ent, p_gi_rel);

    // 2) GRU aggregation, packed bf16x2, 2 x LDG.128 per item
    aggregate_kernel<<<dim3(2, BB), 1024, AGG_SMEM>>>(
        node_emb, p_gi_rel, p_gi_ent, p_gh,
        (const int2*)nbrs, nb_num, aim_nd, out);
}

// round 16
// speedup vs baseline: 1.1493x; 1.1493x over previous
#include <cuda_runtime.h>
#include <cstdint>

// Problem constants
#define BB      128
#define TOPK    32
#define MN      64
#define NODES   258        // MAX_NODES + 2
#define HDIM    128
#define G3      384        // 3*H

// ---------------------------------------------------------------------------
// Device scratch
// ---------------------------------------------------------------------------
__device__ uint32_t g_gi_rel32[400 * 256];        // bf16x2 [rel][pair(64)][4]: r,z,n,pad
__device__ uint32_t g_gi_ent32[BB * TOPK * 192];  // bf16x2 [t][gate(3)][pair(64)]
__device__ uint16_t g_gh16 [BB * NODES * G3];     // gh in bf16 [node][gate][ch]

// ---------------------------------------------------------------------------
// Helpers
// ---------------------------------------------------------------------------
__device__ __forceinline__ uint32_t f2bf2(float lo, float hi) {
    uint32_t r;
    asm("cvt.rn.bf16x2.f32 %0, %1, %2;" : "=r"(r) : "f"(hi), "f"(lo));
    return r;
}
__device__ __forceinline__ uint32_t badd2(uint32_t a, uint32_t b) {
    uint32_t r; asm("add.rn.bf16x2 %0, %1, %2;" : "=r"(r) : "r"(a), "r"(b)); return r;
}
__device__ __forceinline__ uint32_t bsub2(uint32_t a, uint32_t b) {
    uint32_t r; asm("sub.rn.bf16x2 %0, %1, %2;" : "=r"(r) : "r"(a), "r"(b)); return r;
}
__device__ __forceinline__ uint32_t bmul2(uint32_t a, uint32_t b) {
    uint32_t r; asm("mul.rn.bf16x2 %0, %1, %2;" : "=r"(r) : "r"(a), "r"(b)); return r;
}
__device__ __forceinline__ uint32_t bfma2(uint32_t a, uint32_t b, uint32_t c) {
    uint32_t r; asm("fma.rn.bf16x2 %0, %1, %2, %3;" : "=r"(r) : "r"(a), "r"(b), "r"(c)); return r;
}
__device__ __forceinline__ uint32_t btanh2(uint32_t x) {
    uint32_t r; asm("tanh.approx.bf16x2 %0, %1;" : "=r"(r) : "r"(x)); return r;
}
#define BHALF2 0x3F003F00u
__device__ __forceinline__ float blo(uint32_t x) { return __uint_as_float(x << 16); }
__device__ __forceinline__ float bhi(uint32_t x) { return __uint_as_float(x & 0xFFFF0000u); }

__device__ __forceinline__ void mma_bf16(float* d, const uint32_t* a, const uint32_t* b) {
    asm volatile(
        "mma.sync.aligned.m16n8k16.row.col.f32.bf16.bf16.f32 "
        "{%0,%1,%2,%3}, {%4,%5,%6,%7}, {%8,%9}, {%0,%1,%2,%3};"
        : "+f"(d[0]), "+f"(d[1]), "+f"(d[2]), "+f"(d[3])
        : "r"(a[0]), "r"(a[1]), "r"(a[2]), "r"(a[3]), "r"(b[0]), "r"(b[1]));
}

// ---------------------------------------------------------------------------
// Kernel 1: fused bf16 mma.sync GEMM, 294 CTAs (one wave @ 2 CTA/SM).
//   gi_ent branch writes pre-packed bf16x2 [t][gate][pair] (coalesced u32).
//   gh branch unchanged (R14 layout, coalesced).
// ---------------------------------------------------------------------------
#define APITCH 68
#define OFFA    0
#define OFFB    (128 * APITCH * 4)
#define OFFBIAS (OFFB + 128 * APITCH * 4)
#define OFFRIDX (OFFBIAS + 384 * 4)
#define GEMM_SMEM (OFFRIDX + 128 * 4)

__global__ __launch_bounds__(256, 2) void gemm_mma_kernel(
    const float* __restrict__ node_emb,
    const float* __restrict__ ent_tab,
    const float* __restrict__ rel_tab,
    const float* __restrict__ W_ih,
    const float* __restrict__ W_hh,
    const float* __restrict__ b_ih,
    const float* __restrict__ b_hh,
    const int*   __restrict__ aim_ent,
    uint16_t* __restrict__ out_gh,
    uint32_t* __restrict__ out_gi_ent,   // [t][gate][pair] u32
    uint32_t* __restrict__ out_gi_rel)   // [rel][pair][4]
{
    extern __shared__ char sm[];
    uint32_t* As = reinterpret_cast<uint32_t*>(sm + OFFA);
    uint32_t* Bs = reinterpret_cast<uint32_t*>(sm + OFFB);
    float*    sh_bias = reinterpret_cast<float*>(sm + OFFBIAS);
    int*      sh_ridx = reinterpret_cast<int*>(sm + OFFRIDX);

    const int tid  = threadIdx.x;
    const int wid  = tid >> 5;
    const int lane = tid & 31;

    int bx = blockIdx.x;
    const float* A; const int* gather = nullptr; int nrows;
    const float* W; int ldw, woff; const float* bias;
    int tile, obf = 0, orel = 0, oent = 0;
    if (bx < 258) {
        tile = bx;
        A = node_emb; nrows = BB * NODES;
        W = W_hh; ldw = 128; woff = 0; bias = b_hh; obf = 1;
    } else if (bx < 290) {
        tile = bx - 258;
        A = ent_tab; gather = aim_ent; nrows = BB * TOPK;
        W = W_ih; ldw = 256; woff = 0; bias = b_ih; oent = 1;
    } else {
        tile = bx - 290;
        A = rel_tab; nrows = 400;
        W = W_ih; ldw = 256; woff = 128; bias = nullptr; orel = 1;
    }
    const int row0 = tile * 128;

    if (tid < 128) {
        int r = row0 + tid;
        sh_ridx[tid] = (r < nrows) ? (gather ? gather[r] : r) : -1;
    }
    for (int i = tid; i < G3; i += 256)
        sh_bias[i] = bias ? bias[i] : 0.0f;
    __syncthreads();

    // ---- fill A tile once (bf16 pairs) ----
    for (int idx = tid; idx < 128 * 32; idx += 256) {
        int i  = idx >> 5;
        int k4 = (idx & 31) << 2;
        int ridx = sh_ridx[i];
        float4 v = make_float4(0.f, 0.f, 0.f, 0.f);
        if (ridx >= 0)
            v = *reinterpret_cast<const float4*>(&A[(size_t)ridx * 128 + k4]);
        uint2 w = make_uint2(f2bf2(v.x, v.y), f2bf2(v.z, v.w));
        *reinterpret_cast<uint2*>(&As[i * APITCH + (k4 >> 1)]) = w;
    }

    const int quad  = lane >> 2;
    const int tq    = lane & 3;
    const int rbase = (wid >> 2) * 64;
    const int cbase = (wid & 3) * 32;

    for (int gate = 0; gate < 3; gate++) {
        for (int idx = tid; idx < 128 * 32; idx += 256) {
            int n  = idx >> 5;
            int k4 = (idx & 31) << 2;
            float4 v = *reinterpret_cast<const float4*>(
                &W[(size_t)(gate * 128 + n) * ldw + woff + k4]);
            uint2 w = make_uint2(f2bf2(v.x, v.y), f2bf2(v.z, v.w));
            *reinterpret_cast<uint2*>(&Bs[n * APITCH + (k4 >> 1)]) = w;
        }
        __syncthreads();

        float acc[4][4][4];
#pragma unroll
        for (int mt = 0; mt < 4; mt++)
#pragma unroll
            for (int nt = 0; nt < 4; nt++)
#pragma unroll
                for (int r = 0; r < 4; r++) acc[mt][nt][r] = 0.f;

#pragma unroll
        for (int ks = 0; ks < 8; ks++) {
            const int k0 = ks * 8;
            uint32_t af[4][4];
#pragma unroll
            for (int mt = 0; mt < 4; mt++) {
                int r = rbase + mt * 16 + quad;
                af[mt][0] = As[r * APITCH + k0 + tq];
                af[mt][1] = As[(r + 8) * APITCH + k0 + tq];
                af[mt][2] = As[r * APITCH + k0 + tq + 4];
                af[mt][3] = As[(r + 8) * APITCH + k0 + tq + 4];
            }
            uint32_t bf[4][2];
#pragma unroll
            for (int nt = 0; nt < 4; nt++) {
                int c = cbase + nt * 8 + quad;
                bf[nt][0] = Bs[c * APITCH + k0 + tq];
                bf[nt][1] = Bs[c * APITCH + k0 + tq + 4];
            }
#pragma unroll
            for (int mt = 0; mt < 4; mt++)
#pragma unroll
                for (int nt = 0; nt < 4; nt++)
                    mma_bf16(acc[mt][nt], af[mt], bf[nt]);
        }

#pragma unroll
        for (int mt = 0; mt < 4; mt++) {
#pragma unroll
            for (int nt = 0; nt < 4; nt++) {
                const int col = cbase + nt * 8 + tq * 2;
                const float b0 = sh_bias[gate * 128 + col];
                const float b1 = sh_bias[gate * 128 + col + 1];
                const int r1 = row0 + rbase + mt * 16 + quad;
                const int r2 = r1 + 8;
                if (obf) {
                    if (r1 < nrows)
                        *reinterpret_cast<uint32_t*>(
                            &out_gh[(size_t)r1 * G3 + gate * 128 + col]) =
                            f2bf2(acc[mt][nt][0] + b0, acc[mt][nt][1] + b1);
                    if (r2 < nrows)
                        *reinterpret_cast<uint32_t*>(
                            &out_gh[(size_t)r2 * G3 + gate * 128 + col]) =
                            f2bf2(acc[mt][nt][2] + b0, acc[mt][nt][3] + b1);
                } else if (orel) {
                    if (r1 < nrows)
                        out_gi_rel[(size_t)r1 * 256 + (col >> 1) * 4 + gate] =
                            f2bf2(acc[mt][nt][0] + b0, acc[mt][nt][1] + b1);
                    if (r2 < nrows)
                        out_gi_rel[(size_t)r2 * 256 + (col >> 1) * 4 + gate] =
                            f2bf2(acc[mt][nt][2] + b0, acc[mt][nt][3] + b1);
                } else {
                    // gi_ent: [t][gate][pair] u32 — consecutive tq -> +4B, coalesced
                    if (r1 < nrows)
                        out_gi_ent[(size_t)r1 * 192 + gate * 64 + (col >> 1)] =
                            f2bf2(acc[mt][nt][0] + b0, acc[mt][nt][1] + b1);
                    if (r2 < nrows)
                        out_gi_ent[(size_t)r2 * 192 + gate * 64 + (col >> 1)] =
                            f2bf2(acc[mt][nt][2] + b0, acc[mt][nt][3] + b1);
                }
            }
        }
        __syncthreads();
    }
}

// ---------------------------------------------------------------------------
// Kernel 2: GRU aggregation (R14 structure), packed bf16x2, gh via per-item
// L2 loads, h staged in smem. Main/tail loop split (no per-item predication).
// CTA = (batch, 64-ch chunk); 1024 threads; lane owns a channel pair.
// ---------------------------------------------------------------------------
#define OFF_H    0                               // bf16x2 [258*32] = 33024
#define OFF_GIR  33024                           // u32 [32*32] = 4096
#define OFF_GIZ  37120
#define OFF_GIN  41216
#define OFF_WORK 45312                           // i32 [2048] = 8192
#define OFF_ACC  53504                           // f32 [32*64] = 8192
#define OFF_PREF 61696                           // i32 [33] pad 144
#define OFF_NUM  61840
#define OFF_AIM  61968
#define AGG_SMEM 62096

__global__ __launch_bounds__(1024, 1) void aggregate_kernel(
    const float*    __restrict__ node_emb,
    const uint32_t* __restrict__ gi_rel32,
    const uint32_t* __restrict__ gi_ent32,      // [t][gate][pair]
    const uint32_t* __restrict__ gh32,          // gh as u32 pairs, row = 192 u32
    const int2*     __restrict__ neighbors,
    const int*      __restrict__ nb_num,
    const int*      __restrict__ aim_nodes,
    float* __restrict__ out)
{
    extern __shared__ char smraw[];
    uint32_t* sh_h    = reinterpret_cast<uint32_t*>(smraw + OFF_H);
    uint32_t* sh_gir  = reinterpret_cast<uint32_t*>(smraw + OFF_GIR);
    uint32_t* sh_giz  = reinterpret_cast<uint32_t*>(smraw + OFF_GIZ);
    uint32_t* sh_gin  = reinterpret_cast<uint32_t*>(smraw + OFF_GIN);
    int*      sh_work = reinterpret_cast<int*>(smraw + OFF_WORK);
    float*    sh_acc  = reinterpret_cast<float*>(smraw + OFF_ACC);
    int*      sh_pref = reinterpret_cast<int*>(smraw + OFF_PREF);
    int*      sh_num  = reinterpret_cast<int*>(smraw + OFF_NUM);
    int*      sh_aim  = reinterpret_cast<int*>(smraw + OFF_AIM);

    const int tid = threadIdx.x;
    const int c   = blockIdx.x;        // 64-channel chunk (0..1)
    const int b   = blockIdx.y;
    const int cc0 = c * 64;

    // ---- h slice (bf16x2) + fused base copy ----
    for (int idx = tid; idx < 258 * 16; idx += 1024) {
        int n = idx >> 4, q = idx & 15;
        float4 v = *reinterpret_cast<const float4*>(
            &node_emb[((size_t)b * NODES + n) * HDIM + cc0 + q * 4]);
        *reinterpret_cast<float4*>(&out[((size_t)b * NODES + n) * HDIM + cc0 + q * 4]) = v;
        uint2 w = make_uint2(f2bf2(v.x, v.y), f2bf2(v.z, v.w));
        *reinterpret_cast<uint2*>(&sh_h[n * 32 + q * 2]) = w;
    }
    // ---- gi_ent: direct packed uint4 copy from [t][gate][pair] ----
    for (int idx = tid; idx < 32 * 24; idx += 1024) {
        int t = idx / 24, q = idx % 24;
        int gate = q >> 3, p4 = (q & 7) * 4;
        uint4 v = *reinterpret_cast<const uint4*>(
            &gi_ent32[((size_t)b * TOPK + t) * 192 + gate * 64 + c * 32 + p4]);
        uint32_t* dst = (gate == 0 ? sh_gir : gate == 1 ? sh_giz : sh_gin);
        *reinterpret_cast<uint4*>(&dst[t * 32 + p4]) = v;
    }
    for (int idx = tid; idx < 2048; idx += 1024)
        sh_acc[idx] = 0.0f;
    if (tid < 32)
        sh_num[tid] = nb_num[b * TOPK + tid];
    if (tid >= 32 && tid < 64) {
        int t = tid - 32;
        int node = aim_nodes[b * TOPK + t];
        unsigned grp = __match_any_sync(0xFFFFFFFFu, node);
        int winner = (31 - __clz(grp)) == t;
        sh_aim[t] = winner ? node : -1;
    }
    __syncthreads();

    // ---- prefix scan over num (warp 0) ----
    if (tid < 32) {
        int s = sh_num[tid];
#pragma unroll
        for (int o = 1; o < 32; o <<= 1) {
            int x = __shfl_up_sync(0xFFFFFFFFu, s, o);
            if (tid >= o) s += x;
        }
        sh_pref[tid + 1] = s;
        if (tid == 0) sh_pref[0] = 0;
    }
    __syncthreads();

    const int V = sh_pref[32];

    // ---- worklist build ----
    for (int idx = tid; idx < TOPK * MN; idx += 1024) {
        int t = idx >> 6, m = idx & 63;
        if (m < sh_num[t]) {
            int2 nb = neighbors[(size_t)b * TOPK * MN + idx];
            sh_work[sh_pref[t] + m] = t | (nb.x << 5) | (nb.y << 15);
        }
    }
    __syncthreads();

    // ---- balanced compute: 32 warps; gh gates via per-item L2 loads ----
    const int warp = tid >> 5;
    const int lane = tid & 31;
    const int vbeg = (V * warp) >> 5;
    const int vend = (V * (warp + 1)) >> 5;

    const uint32_t* base_g  = gi_rel32 + (c * 32 + lane) * 4;
    const uint32_t* base_gh = gh32 + (size_t)b * NODES * 192 + c * 32 + lane;

    int   cur_t = -1;
    uint32_t gir = 0, giz = 0, gin = 0;
    float acc0 = 0.f, acc1 = 0.f;

    int v0 = vbeg;
    // main loop: full batches of 4, unpredicated
    for (; v0 + 4 <= vend; v0 += 4) {
        int w[4]; uint4 gv[4];
        uint32_t gr[4], gz[4], gn[4];
#pragma unroll
        for (int j = 0; j < 4; j++) {
            w[j] = sh_work[v0 + j];
            int rel = w[j] >> 15;
            int nd  = (w[j] >> 5) & 1023;
            gv[j] = __ldg(reinterpret_cast<const uint4*>(base_g + rel * 256));
            const uint32_t* p = base_gh + nd * 192;
            gr[j] = __ldg(p);
            gz[j] = __ldg(p + 64);
            gn[j] = __ldg(p + 128);
        }
#pragma unroll
        for (int j = 0; j < 4; j++) {
            int t = w[j] & 31;
            if (t != cur_t) {               // warp-uniform
                if (cur_t >= 0) {
                    atomicAdd(&sh_acc[cur_t * 64 + 2 * lane],     acc0);
                    atomicAdd(&sh_acc[cur_t * 64 + 2 * lane + 1], acc1);
                }
                acc0 = acc1 = 0.f;
                cur_t = t;
                gir = sh_gir[t * 32 + lane];
                giz = sh_giz[t * 32 + lane];
                gin = sh_gin[t * 32 + lane];
            }
            int nd = (w[j] >> 5) & 1023;
            uint32_t hh = sh_h[nd * 32 + lane];
            uint32_t pre_r = badd2(badd2(gir, gv[j].x), gr[j]);
            uint32_t r = bfma2(btanh2(bmul2(pre_r, BHALF2)), BHALF2, BHALF2);
            uint32_t pre_z = badd2(badd2(giz, gv[j].y), gz[j]);
            uint32_t z = bfma2(btanh2(bmul2(pre_z, BHALF2)), BHALF2, BHALF2);
            uint32_t pre_n = bfma2(r, gn[j], badd2(gin, gv[j].z));
            uint32_t n = btanh2(pre_n);
            uint32_t hn = bfma2(z, bsub2(hh, n), n);
            acc0 += blo(hn);
            acc1 += bhi(hn);
        }
    }
    // tail: up to 3 items, scalar
    for (; v0 < vend; v0++) {
        int w = sh_work[v0];
        int t = w & 31;
        if (t != cur_t) {
            if (cur_t >= 0) {
                atomicAdd(&sh_acc[cur_t * 64 + 2 * lane],     acc0);
                atomicAdd(&sh_acc[cur_t * 64 + 2 * lane + 1], acc1);
            }
            acc0 = acc1 = 0.f;
            cur_t = t;
            gir = sh_gir[t * 32 + lane];
            giz = sh_giz[t * 32 + lane];
            gin = sh_gin[t * 32 + lane];
        }
        int rel = w >> 15;
        int nd  = (w >> 5) & 1023;
        uint4 gv = __ldg(reinterpret_cast<const uint4*>(base_g + rel * 256));
        const uint32_t* p = base_gh + nd * 192;
        uint32_t gr = __ldg(p), gz = __ldg(p + 64), gn = __ldg(p + 128);
        uint32_t hh = sh_h[nd * 32 + lane];
        uint32_t pre_r = badd2(badd2(gir, gv.x), gr);
        uint32_t r = bfma2(btanh2(bmul2(pre_r, BHALF2)), BHALF2, BHALF2);
        uint32_t pre_z = badd2(badd2(giz, gv.y), gz);
        uint32_t z = bfma2(btanh2(bmul2(pre_z, BHALF2)), BHALF2, BHALF2);
        uint32_t pre_n = bfma2(r, gn, badd2(gin, gv.z));
        uint32_t n = btanh2(pre_n);
        uint32_t hn = bfma2(z, bsub2(hh, n), n);
        acc0 += blo(hn);
        acc1 += bhi(hn);
    }
    if (cur_t >= 0) {
        atomicAdd(&sh_acc[cur_t * 64 + 2 * lane],     acc0);
        atomicAdd(&sh_acc[cur_t * 64 + 2 * lane + 1], acc1);
    }
    __syncthreads();

    // ---- epilogue: mean + scatter winners (warp t) ----
    {
        const int t = warp;
        const int aim = sh_aim[t];
        if (aim >= 0) {
            const int num = sh_num[t];
            float inv = (num > 0) ? 1.0f / (float)num : 0.f;
            float2 u = make_float2(sh_acc[t * 64 + 2 * lane] * inv,
                                   sh_acc[t * 64 + 2 * lane + 1] * inv);
            *reinterpret_cast<float2*>(
                &out[((size_t)b * NODES + aim) * HDIM + cc0 + 2 * lane]) = u;
        }
    }
}

// ---------------------------------------------------------------------------
// Host launcher
// ---------------------------------------------------------------------------
extern "C" void kernel_launch(void* const* d_in, const int* in_sizes, int n_in,
                              void* d_out, int out_size)
{
    const float* node_emb = (const float*)d_in[0];
    const float* ent_tab  = (const float*)d_in[1];
    const float* rel_tab  = (const float*)d_in[2];
    const float* W_ih     = (const float*)d_in[3];
    const float* W_hh     = (const float*)d_in[4];
    const float* b_ih     = (const float*)d_in[5];
    const float* b_hh     = (const float*)d_in[6];
    const int*   aim_nd   = (const int*)d_in[7];
    const int*   aim_ent  = (const int*)d_in[8];
    const int*   nbrs     = (const int*)d_in[9];
    const int*   nb_num   = (const int*)d_in[10];
    float* out = (float*)d_out;

    uint32_t *p_gi_rel, *p_gi_ent; uint16_t* p_gh;
    cudaGetSymbolAddress((void**)&p_gi_rel, g_gi_rel32);
    cudaGetSymbolAddress((void**)&p_gi_ent, g_gi_ent32);
    cudaGetSymbolAddress((void**)&p_gh,     g_gh16);

    cudaFuncSetAttribute(gemm_mma_kernel,
        cudaFuncAttributeMaxDynamicSharedMemorySize, GEMM_SMEM);
    cudaFuncSetAttribute(aggregate_kernel,
        cudaFuncAttributeMaxDynamicSharedMemorySize, AGG_SMEM);

    // 1) fused GEMMs (bf16 tensor cores, one wave)
    gemm_mma_kernel<<<294, 256, GEMM_SMEM>>>(
        node_emb, ent_tab, rel_tab, W_ih, W_hh, b_ih, b_hh, aim_ent,
        p_gh, p_gi_ent, p_gi_rel);

    // 2) GRU aggregation, packed bf16x2, gh via per-item L2 loads
    aggregate_kernel<<<dim3(2, BB), 1024, AGG_SMEM>>>(
        node_emb, p_gi_rel, p_gi_ent, (const uint32_t*)p_gh,
        (const int2*)nbrs, nb_num, aim_nd, out);
}